// round 11
// baseline (speedup 1.0000x reference)
#include <cuda_runtime.h>
#include <cuda_fp16.h>

#define NTOK   4096
#define PDIM   128
#define HEADS  4
#define EDIM   32
#define NSEGS  32
#define KCAP   192     // max segment rows on the fast path
#define QT     64      // queries per attention block
#define QTILES 3
#define PSTR   34      // P row stride in u32 (68 halves -> 8B-aligned rows)
#define QSCALE 0.17677669529663687f
#define NEGINF (-3.0e38f)

typedef unsigned long long ull;

__device__ float g_QKV[3][NTOK * PDIM];
__device__ int   g_idx[NTOK];
__device__ int   g_off[NSEGS + 1];
__device__ int   g_cnt[NSEGS];

// f32x2 packed helpers (sm_103a FFMA2, PTX-only)
__device__ __forceinline__ ull f2pk(float lo, float hi) {
    ull r; asm("mov.b64 %0, {%1, %2};" : "=l"(r) : "f"(lo), "f"(hi)); return r;
}
__device__ __forceinline__ ull ffma2(ull a, ull b, ull c) {
    ull d; asm("fma.rn.f32x2 %0, %1, %2, %3;" : "=l"(d) : "l"(a), "l"(b), "l"(c)); return d;
}
__device__ __forceinline__ void f2un(ull v, float& lo, float& hi) {
    asm("mov.b64 {%0, %1}, %2;" : "=f"(lo), "=f"(hi) : "l"(v));
}
// pack (hi, lo) f32 -> f16x2 word (hi in upper half)
__device__ __forceinline__ unsigned h2pk(float hi, float lo) {
    unsigned r;
    asm("cvt.rn.f16x2.f32 %0, %1, %2;" : "=r"(r) : "f"(hi), "f"(lo));
    return r;
}

// ---------------------------------------------------------------------------
// Fused O(N) stable sort-by-segment (one block, 256 threads)   [R2 verbatim]
// ---------------------------------------------------------------------------
__device__ void sort_block(const int* __restrict__ pos, int* sm) {
    int* spos    = sm;            // 4096
    int* hist    = sm + 4096;     // 4096
    int* warptot = sm + 8192;     // 8
    const int tid = threadIdx.x, lane = tid & 31, w = tid >> 5;

    const int4* pos4 = (const int4*)pos;
    int4 z4 = make_int4(0, 0, 0, 0);
    for (int i = tid; i < NTOK / 4; i += 256) {
        ((int4*)spos)[i] = pos4[i];
        ((int4*)hist)[i] = z4;
    }
    __syncthreads();

    for (int g = w; g < 128; g += 8) {
        int s = spos[g * 32 + lane];
        unsigned mask = __match_any_sync(0xffffffffu, s);
        if (lane == __ffs(mask) - 1) hist[s * 128 + g] = __popc(mask);
    }
    __syncthreads();

    int base = tid * 16;
    int loc[16];
    int run = 0;
#pragma unroll
    for (int i = 0; i < 16; i++) { loc[i] = run; run += hist[base + i]; }
    int s = run;
#pragma unroll
    for (int d = 1; d < 32; d <<= 1) {
        int o = __shfl_up_sync(0xffffffffu, s, d);
        if (lane >= d) s += o;
    }
    int excl = s - run;
    if (lane == 31) warptot[w] = s;
    __syncthreads();
    if (tid == 0) {
        int a = 0;
#pragma unroll
        for (int i = 0; i < 8; i++) { int t = warptot[i]; warptot[i] = a; a += t; }
    }
    __syncthreads();
    int offt = warptot[w] + excl;
#pragma unroll
    for (int i = 0; i < 16; i++) hist[base + i] = offt + loc[i];
    __syncthreads();

    if (tid < NSEGS) {
        int o   = hist[tid * 128];
        int nxt = (tid == NSEGS - 1) ? NTOK : hist[(tid + 1) * 128];
        g_off[tid] = o;
        g_cnt[tid] = nxt - o;
        if (tid == 0) g_off[NSEGS] = NTOK;
    }

    for (int g = w; g < 128; g += 8) {
        int tok = g * 32 + lane;
        int sg = spos[tok];
        unsigned mask = __match_any_sync(0xffffffffu, sg);
        int rank = __popc(mask & ((1u << lane) - 1u));
        g_idx[hist[sg * 128 + g] + rank] = tok;
    }
}

// ---------------------------------------------------------------------------
// QKV projection + fused sort. grid (65, 6). 64x64 tiles.   [R2 verbatim]
// ---------------------------------------------------------------------------
__global__ __launch_bounds__(256)
void qkv_sort_kernel(const float* __restrict__ inp, const int* __restrict__ pos,
                     const float* __restrict__ Wq, const float* __restrict__ bq,
                     const float* __restrict__ Wk, const float* __restrict__ bk,
                     const float* __restrict__ Wv, const float* __restrict__ bv)
{
    extern __shared__ float sm[];
    if (blockIdx.x == 64) {
        if (blockIdx.y == 0) sort_block(pos, (int*)sm);
        return;
    }

    float* As = sm;               // 64 x 128
    float* Bs = sm + 64 * PDIM;   // 128 x 64

    const int which = blockIdx.y >> 1, colh = blockIdx.y & 1;
    const float* W = (which == 0) ? Wq : (which == 1) ? Wk : Wv;
    const float* b = (which == 0) ? bq : (which == 1) ? bk : bv;
    float* outp = g_QKV[which];

    const int row0 = blockIdx.x * 64, col0 = colh * 64;
    const int tid = threadIdx.x;

    const float4* inp4 = (const float4*)(inp + row0 * PDIM);
    const float4* W4 = (const float4*)W;
    for (int i = tid; i < 2048; i += 256) ((float4*)As)[i] = inp4[i];
    for (int i = tid; i < 2048; i += 256) {
        int k = i >> 4, c4 = i & 15;
        ((float4*)Bs)[k * 16 + c4] = W4[k * 32 + colh * 16 + c4];
    }
    __syncthreads();

    const int tx = tid & 15, ty = tid >> 4;

    ull acc[4][2];
#pragma unroll
    for (int i = 0; i < 4; i++) { acc[i][0] = 0ull; acc[i][1] = 0ull; }

    const ulonglong2* Bs2 = (const ulonglong2*)Bs;
#pragma unroll 2
    for (int k = 0; k < PDIM; k++) {
        ulonglong2 bb = Bs2[k * 16 + tx];
#pragma unroll
        for (int i = 0; i < 4; i++) {
            float a = As[(ty * 4 + i) * PDIM + k];
            ull aa = f2pk(a, a);
            acc[i][0] = ffma2(aa, bb.x, acc[i][0]);
            acc[i][1] = ffma2(aa, bb.y, acc[i][1]);
        }
    }

    float4 bias = ((const float4*)(b + col0))[tx];
    float4* out4 = (float4*)outp;
#pragma unroll
    for (int i = 0; i < 4; i++) {
        int row = row0 + ty * 4 + i;
        float x0, x1, x2, x3;
        f2un(acc[i][0], x0, x1);
        f2un(acc[i][1], x2, x3);
        out4[row * 32 + colh * 16 + tx] =
            make_float4(x0 + bias.x, x1 + bias.y, x2 + bias.z, x3 + bias.w);
    }
}

// ---------------------------------------------------------------------------
// Attention per (seg, head, 64-query tile). 256 threads, 3 blocks/SM.
// Scores stay in registers (warp-local softmax via shfl); only post-exp
// weights P stored, as fp16, overlaid on the dead KT/QsT region.
// SMEM: Vs[192][32] KT[32][192] QsT[32][64] sInv[64] = 57600 B -> 3/SM,
// grid 384 <= 444 slots -> single wave.
// ---------------------------------------------------------------------------
__global__ __launch_bounds__(256, 3)
void attn_kernel(float* __restrict__ out)
{
    extern __shared__ float smf[];
    float* Vs   = smf;                        // KCAP*32      = 6144 f
    float* KT   = smf + 6144;                 // 32*KCAP      = 6144 f
    float* QsT  = smf + 12288;                // 32*QT        = 2048 f
    float* sInv = smf + 14336;                // QT
    unsigned* P32 = (unsigned*)(smf + 6144);  // fp16 P[j][q], 192*PSTR u32
                                              // (overlays KT+start of QsT;
                                              //  both dead when P is written)

    const int seg = blockIdx.x, h = blockIdx.y, z = blockIdx.z;
    const int off = g_off[seg];
    const int cnt = g_cnt[seg];
    const int tid = threadIdx.x, lane = tid & 31, w = tid >> 5;

    const float* Q = g_QKV[0];
    const float* K = g_QKV[1];
    const float* V = g_QKV[2];

    if (cnt > KCAP) {
        // fallback: streaming online softmax (correct for any count)
        int gw = z * 8 + w;
        for (int qi = gw; qi < cnt; qi += QTILES * 8) {
            int t = g_idx[off + qi];
            float qv = Q[t * PDIM + h * EDIM + lane] * QSCALE;
            float m = NEGINF, l = 0.f, a = 0.f;
            for (int j = 0; j < cnt; j++) {
                int tj = g_idx[off + j];
                float s = qv * K[tj * PDIM + h * EDIM + lane];
#pragma unroll
                for (int d = 16; d; d >>= 1) s += __shfl_xor_sync(0xffffffffu, s, d);
                float mn  = fmaxf(m, s);
                float cor = __expf(m - mn);
                float pj  = __expf(s - mn);
                l = l * cor + pj;
                a = a * cor + pj * V[tj * PDIM + h * EDIM + lane];
                m = mn;
            }
            out[t * PDIM + h * EDIM + lane] = a / l;
        }
        return;
    }

    const int nq = min(QT, cnt - z * QT);
    if (nq <= 0) return;

    // gather K (transposed) + V   [R2 layout]
    for (int i = tid; i < cnt * 8; i += 256) {
        int r = i >> 3, c = i & 7;
        int t = g_idx[off + r];
        float4 kf = *(const float4*)(K + t * PDIM + h * EDIM + c * 4);
        KT[(c * 4 + 0) * KCAP + r] = kf.x;
        KT[(c * 4 + 1) * KCAP + r] = kf.y;
        KT[(c * 4 + 2) * KCAP + r] = kf.z;
        KT[(c * 4 + 3) * KCAP + r] = kf.w;
        *(float4*)&Vs[r * EDIM + c * 4] = *(const float4*)(V + t * PDIM + h * EDIM + c * 4);
    }
    // gather Q tile (transposed, pre-scaled) + zero tail
    for (int i = tid; i < nq * 8; i += 256) {
        int q = i >> 3, c = i & 7;
        int t = g_idx[off + z * QT + q];
        float4 qf = *(const float4*)(Q + t * PDIM + h * EDIM + c * 4);
        QsT[(c * 4 + 0) * QT + q] = qf.x * QSCALE;
        QsT[(c * 4 + 1) * QT + q] = qf.y * QSCALE;
        QsT[(c * 4 + 2) * QT + q] = qf.z * QSCALE;
        QsT[(c * 4 + 3) * QT + q] = qf.w * QSCALE;
    }
    for (int i = tid; i < (QT - nq) * 8; i += 256) {
        int q = nq + (i >> 3), c = i & 7;
#pragma unroll
        for (int cc = 0; cc < 4; cc++) QsT[(c * 4 + cc) * QT + q] = 0.f;
    }
    __syncthreads();

    // ---- GEMM1 (scores in registers): warp w owns queries w*8..w*8+7,
    //      lane kx owns keys kx+32r, r=0..5 ----
    {
        const int kx = lane;
        const int wq = w << 3;
        ull acc[4][6];
#pragma unroll
        for (int i = 0; i < 4; i++)
#pragma unroll
            for (int r = 0; r < 6; r++) acc[i][r] = 0ull;

#pragma unroll 2
        for (int e = 0; e < EDIM; e++) {
            const float* qe  = QsT + e * QT + wq;
            ull qp[4];
#pragma unroll
            for (int i = 0; i < 4; i++) {
                float2 qv = *(const float2*)(qe + 2 * i);   // warp-uniform broadcast
                qp[i] = f2pk(qv.x, qv.y);
            }
            const float* kte = KT + e * KCAP + kx;
#pragma unroll
            for (int r = 0; r < 6; r++) {
                float kv = kte[32 * r];                     // 32 banks, conflict-free
                ull kk = f2pk(kv, kv);
                acc[0][r] = ffma2(qp[0], kk, acc[0][r]);
                acc[1][r] = ffma2(qp[1], kk, acc[1][r]);
                acc[2][r] = ffma2(qp[2], kk, acc[2][r]);
                acc[3][r] = ffma2(qp[3], kk, acc[3][r]);
            }
        }
        __syncthreads();   // all KT/QsT reads complete -> P may overwrite

        // ---- warp-local softmax + fp16 P store ----
        const int lim = cnt - kx;      // key kx+32r valid iff 32r < lim
#pragma unroll
        for (int i = 0; i < 4; i++) {
            float lo[6], hi[6];
#pragma unroll
            for (int r = 0; r < 6; r++) {
                float a, b;
                f2un(acc[i][r], a, b);
                bool v = (32 * r) < lim;
                lo[r] = v ? a : NEGINF;
                hi[r] = v ? b : NEGINF;
            }
            float ml = lo[0], mh = hi[0];
#pragma unroll
            for (int r = 1; r < 6; r++) { ml = fmaxf(ml, lo[r]); mh = fmaxf(mh, hi[r]); }
#pragma unroll
            for (int d = 16; d; d >>= 1) {
                ml = fmaxf(ml, __shfl_xor_sync(0xffffffffu, ml, d));
                mh = fmaxf(mh, __shfl_xor_sync(0xffffffffu, mh, d));
            }
            float pl[6], ph[6];
            float sl = 0.f, sh = 0.f;
#pragma unroll
            for (int r = 0; r < 6; r++) {
                pl[r] = __expf(lo[r] - ml);   // NEGINF -> 0
                ph[r] = __expf(hi[r] - mh);
                sl += pl[r];
                sh += ph[r];
            }
#pragma unroll
            for (int d = 16; d; d >>= 1) {
                sl += __shfl_xor_sync(0xffffffffu, sl, d);
                sh += __shfl_xor_sync(0xffffffffu, sh, d);
            }
#pragma unroll
            for (int r = 0; r < 6; r++)
                P32[(kx + 32 * r) * PSTR + (wq >> 1) + i] = h2pk(ph[r], pl[r]);
            if (kx == 0) {
                sInv[wq + 2 * i]     = 1.f / sl;
                sInv[wq + 2 * i + 1] = 1.f / sh;
            }
        }
    }
    __syncthreads();

    // ---- GEMM2: O[q][e] = sum_j P[j][q]*V[j][e]  (pairs along q) ----
    const int tx = tid & 15, ty = tid >> 4;
    ull o00 = 0ull, o01 = 0ull, o10 = 0ull, o11 = 0ull;
#pragma unroll 4
    for (int j = 0; j < cnt; j++) {
        uint2 pw = *(const uint2*)&P32[j * PSTR + ty * 2];   // broadcast (2 addrs/warp)
        float2 f0 = __half22float2(*(const __half2*)&pw.x);  // (q0, q1)
        float2 f1 = __half22float2(*(const __half2*)&pw.y);  // (q2, q3)
        ull ppa = f2pk(f0.x, f0.y);
        ull ppb = f2pk(f1.x, f1.y);
        float2 v = *(const float2*)&Vs[j * EDIM + tx * 2];
        ull v0 = f2pk(v.x, v.x);
        ull v1 = f2pk(v.y, v.y);
        o00 = ffma2(ppa, v0, o00);
        o01 = ffma2(ppa, v1, o01);
        o10 = ffma2(ppb, v0, o10);
        o11 = ffma2(ppb, v1, o11);
    }

    // ---- epilogue  [R2 verbatim] ----
    {
        int e0 = h * EDIM + tx * 2;
        float a0e0, a1e0, a0e1, a1e1;
        f2un(o00, a0e0, a1e0);
        f2un(o01, a0e1, a1e1);
        int qa = ty * 4, qb = ty * 4 + 1;
        if (qa < nq) {
            int t = g_idx[off + z * QT + qa]; float iv = sInv[qa];
            out[t * PDIM + e0] = a0e0 * iv; out[t * PDIM + e0 + 1] = a0e1 * iv;
        }
        if (qb < nq) {
            int t = g_idx[off + z * QT + qb]; float iv = sInv[qb];
            out[t * PDIM + e0] = a1e0 * iv; out[t * PDIM + e0 + 1] = a1e1 * iv;
        }
        f2un(o10, a0e0, a1e0);
        f2un(o11, a0e1, a1e1);
        qa = ty * 4 + 2; qb = ty * 4 + 3;
        if (qa < nq) {
            int t = g_idx[off + z * QT + qa]; float iv = sInv[qa];
            out[t * PDIM + e0] = a0e0 * iv; out[t * PDIM + e0 + 1] = a0e1 * iv;
        }
        if (qb < nq) {
            int t = g_idx[off + z * QT + qb]; float iv = sInv[qb];
            out[t * PDIM + e0] = a1e0 * iv; out[t * PDIM + e0 + 1] = a1e1 * iv;
        }
    }
}

// ---------------------------------------------------------------------------
extern "C" void kernel_launch(void* const* d_in, const int* in_sizes, int n_in,
                              void* d_out, int out_size)
{
    const float* inp = (const float*)d_in[0];
    const int*   pos = (const int*)  d_in[1];
    const float* Wq  = (const float*)d_in[2];
    const float* bq  = (const float*)d_in[3];
    const float* Wk  = (const float*)d_in[4];
    const float* bk  = (const float*)d_in[5];
    const float* Wv  = (const float*)d_in[6];
    const float* bv  = (const float*)d_in[7];
    float* out = (float*)d_out;

    const int qkv_smem  = (64 * PDIM + PDIM * 64) * 4;                 // 65536
    const int attn_smem = (14336 + QT) * 4;                            // 57600

    cudaFuncSetAttribute(qkv_sort_kernel, cudaFuncAttributeMaxDynamicSharedMemorySize, qkv_smem);
    cudaFuncSetAttribute(attn_kernel,     cudaFuncAttributeMaxDynamicSharedMemorySize, attn_smem);

    qkv_sort_kernel<<<dim3(65, 6), 256, qkv_smem>>>(inp, pos, Wq, bq, Wk, bk, Wv, bv);
    attn_kernel<<<dim3(NSEGS, HEADS, QTILES), 256, attn_smem>>>(out);
}